// round 1
// baseline (speedup 1.0000x reference)
#include <cuda_runtime.h>
#include <math.h>

#define HIDDEN 2048
#define NH 16
#define NKV 4
#define HD 128
#define BB 2
#define TT 2048
#define MTOT (BB*TT)            // 4096 total rows (B*T)
#define QDIM (NH*HD)            // 2048
#define KVDIM (2*NKV*HD)        // 1024

// Scratch (allocation-free): 32MB + 16MB + 32MB
__device__ float g_Q [MTOT * QDIM];    // [b*T+t][h*128+d]
__device__ float g_KV[MTOT * KVDIM];   // [b*T+t][ (k: kv*128+d) | (v: 512+kv*128+d) ]
__device__ float g_O [MTOT * QDIM];    // attention output, [b*T+t][h*128+d]

// ---------------------------------------------------------------------------
// SGEMM: C[M,N] = A[M,K] * B[N,K]^T   (A,B,C row-major; "NT" layout)
// BM=BN=128, BK=16, 256 threads, 8x8 micro-tile per thread.
// ---------------------------------------------------------------------------
__global__ __launch_bounds__(256) void sgemm_nt(const float* __restrict__ A,
                                                const float* __restrict__ B,
                                                float* __restrict__ C,
                                                int M, int N, int K)
{
    const int BM = 128, BN = 128, BK = 16;
    __shared__ float As[BK][BM + 4];
    __shared__ float Bs[BK][BN + 4];

    const int tid = threadIdx.x;
    const int bm = blockIdx.y * BM;
    const int bn = blockIdx.x * BN;
    const int tx = tid & 15;        // 0..15
    const int ty = tid >> 4;        // 0..15

    const int lrow = tid >> 2;          // 0..63
    const int lcol = (tid & 3) * 4;     // 0,4,8,12

    float acc[8][8];
#pragma unroll
    for (int i = 0; i < 8; i++)
#pragma unroll
        for (int j = 0; j < 8; j++) acc[i][j] = 0.f;

    for (int k0 = 0; k0 < K; k0 += BK) {
#pragma unroll
        for (int h = 0; h < 2; h++) {
            int r = lrow + h * 64;
            float4 a = *(const float4*)(A + (size_t)(bm + r) * K + k0 + lcol);
            As[lcol + 0][r] = a.x; As[lcol + 1][r] = a.y;
            As[lcol + 2][r] = a.z; As[lcol + 3][r] = a.w;
            float4 b = *(const float4*)(B + (size_t)(bn + r) * K + k0 + lcol);
            Bs[lcol + 0][r] = b.x; Bs[lcol + 1][r] = b.y;
            Bs[lcol + 2][r] = b.z; Bs[lcol + 3][r] = b.w;
        }
        __syncthreads();

#pragma unroll
        for (int k = 0; k < BK; k++) {
            float rm[8], rn[8];
#pragma unroll
            for (int i = 0; i < 8; i++) rm[i] = As[k][ty * 8 + i];
#pragma unroll
            for (int j = 0; j < 8; j++) rn[j] = Bs[k][tx * 8 + j];
#pragma unroll
            for (int i = 0; i < 8; i++)
#pragma unroll
                for (int j = 0; j < 8; j++)
                    acc[i][j] += rm[i] * rn[j];
        }
        __syncthreads();
    }

#pragma unroll
    for (int i = 0; i < 8; i++) {
        int r = bm + ty * 8 + i;
        float4 c0 = make_float4(acc[i][0], acc[i][1], acc[i][2], acc[i][3]);
        float4 c1 = make_float4(acc[i][4], acc[i][5], acc[i][6], acc[i][7]);
        *(float4*)(C + (size_t)r * N + bn + tx * 8)     = c0;
        *(float4*)(C + (size_t)r * N + bn + tx * 8 + 4) = c1;
    }
}

// ---------------------------------------------------------------------------
// Flash attention (causal, GQA).
// Grid: (T/64, B*NH). 256 threads = 8 warps; warp owns 8 query rows.
// Lane (r_in = lane>>2, cg = lane&3): S cols c = cg + 4j (j<16),
// O col-chunks c4 = cg + 4i (i<8). Pads chosen for conflict-free LDS.
// ---------------------------------------------------------------------------
#define QS_STRIDE 132
#define KS_STRIDE 136
#define VS_STRIDE 132
#define PS_STRIDE 65
#define ATTN_SMEM ((64*(QS_STRIDE+KS_STRIDE+VS_STRIDE+PS_STRIDE))*4)

__global__ __launch_bounds__(256) void attn_kernel(const float* __restrict__ Q,
                                                   const float* __restrict__ KV,
                                                   float* __restrict__ O)
{
    extern __shared__ float sm[];
    float* Qs = sm;                       // 64 x 132
    float* Ks = Qs + 64 * QS_STRIDE;      // 64 x 136
    float* Vs = Ks + 64 * KS_STRIDE;      // 64 x 132
    float* Ps = Vs + 64 * VS_STRIDE;      // 64 x 65

    const int bh  = blockIdx.y;
    const int b   = bh / NH;
    const int h   = bh % NH;
    const int kvh = h / (NH / NKV);
    const int qm  = blockIdx.x * 64;

    const int tid  = threadIdx.x;
    const int w    = tid >> 5;
    const int lane = tid & 31;
    const int r_in = lane >> 2;
    const int cg   = lane & 3;
    const int row  = w * 8 + r_in;     // 0..63 within tile
    const int qrow = qm + row;         // global query index

    // load Q tile [64 x 128]
    for (int i = tid; i < 64 * 32; i += 256) {
        int r = i >> 5, c4 = i & 31;
        float4 v = *(const float4*)(Q + (size_t)(b * TT + qm + r) * QDIM + h * HD + c4 * 4);
        *(float4*)(Qs + r * QS_STRIDE + c4 * 4) = v;
    }

    float m_old = -INFINITY, l = 0.f;
    float acc[32];
#pragma unroll
    for (int i = 0; i < 32; i++) acc[i] = 0.f;

    const float scale = 0.08838834764831845f;   // 1/sqrt(128)
    const float* Kbase = KV + (size_t)b * TT * KVDIM + kvh * HD;
    const float* Vbase = Kbase + NKV * HD;      // +512
    const int ntiles = qm / 64 + 1;

    for (int t = 0; t < ntiles; t++) {
        const int n0 = t * 64;
        __syncthreads();   // prior iteration done reading Ks/Vs
        for (int i = tid; i < 64 * 32; i += 256) {
            int r = i >> 5, c4 = i & 31;
            const float* src = Kbase + (size_t)(n0 + r) * KVDIM + c4 * 4;
            *(float4*)(Ks + r * KS_STRIDE + c4 * 4) = *(const float4*)src;
            *(float4*)(Vs + r * VS_STRIDE + c4 * 4) = *(const float4*)(src + NKV * HD);
        }
        __syncthreads();

        // S = Q K^T for this lane: row `row`, cols cg + 4j
        float s[16];
#pragma unroll
        for (int j = 0; j < 16; j++) s[j] = 0.f;
#pragma unroll 8
        for (int dc = 0; dc < 32; dc++) {
            float4 q4 = *(float4*)(Qs + row * QS_STRIDE + dc * 4);
#pragma unroll
            for (int j = 0; j < 16; j++) {
                float4 k4 = *(float4*)(Ks + (cg + 4 * j) * KS_STRIDE + dc * 4);
                s[j] += q4.x * k4.x + q4.y * k4.y + q4.z * k4.z + q4.w * k4.w;
            }
        }

        // scale + causal mask
#pragma unroll
        for (int j = 0; j < 16; j++) {
            int kcol = n0 + cg + 4 * j;
            s[j] = (kcol <= qrow) ? s[j] * scale : -INFINITY;
        }

        // online softmax
        float mt = s[0];
#pragma unroll
        for (int j = 1; j < 16; j++) mt = fmaxf(mt, s[j]);
        mt = fmaxf(mt, __shfl_xor_sync(0xffffffffu, mt, 1));
        mt = fmaxf(mt, __shfl_xor_sync(0xffffffffu, mt, 2));
        float m_new = fmaxf(m_old, mt);
        float alpha = __expf(m_old - m_new);
        float ls = 0.f;
#pragma unroll
        for (int j = 0; j < 16; j++) {
            float p = __expf(s[j] - m_new);
            s[j] = p;
            ls += p;
        }
        ls += __shfl_xor_sync(0xffffffffu, ls, 1);
        ls += __shfl_xor_sync(0xffffffffu, ls, 2);
        l = l * alpha + ls;
        m_old = m_new;

        // publish P (each warp writes+reads only its own 8 rows)
#pragma unroll
        for (int j = 0; j < 16; j++) Ps[row * PS_STRIDE + cg + 4 * j] = s[j];
        __syncwarp();

        // O update
#pragma unroll
        for (int i = 0; i < 32; i++) acc[i] *= alpha;
        for (int c = 0; c < 64; c++) {
            float p = Ps[row * PS_STRIDE + c];
#pragma unroll
            for (int i = 0; i < 8; i++) {
                float4 v4 = *(float4*)(Vs + c * VS_STRIDE + (cg + 4 * i) * 4);
                acc[i * 4 + 0] += p * v4.x;
                acc[i * 4 + 1] += p * v4.y;
                acc[i * 4 + 2] += p * v4.z;
                acc[i * 4 + 3] += p * v4.w;
            }
        }
    }

    const float inv_l = 1.f / l;
    float* Op = O + (size_t)(b * TT + qm + row) * QDIM + h * HD;
#pragma unroll
    for (int i = 0; i < 8; i++) {
        float4 v = make_float4(acc[i * 4 + 0] * inv_l, acc[i * 4 + 1] * inv_l,
                               acc[i * 4 + 2] * inv_l, acc[i * 4 + 3] * inv_l);
        *(float4*)(Op + (cg + 4 * i) * 4) = v;
    }
}

// ---------------------------------------------------------------------------

extern "C" void kernel_launch(void* const* d_in, const int* in_sizes, int n_in,
                              void* d_out, int out_size)
{
    const float* x   = (const float*)d_in[0];   // [2,2048,2048]
    const float* wq  = (const float*)d_in[1];   // [2048,2048]
    const float* wkv = (const float*)d_in[2];   // [1024,2048]
    const float* wo  = (const float*)d_in[3];   // [2048,2048]
    float* out = (float*)d_out;                 // [2,2048,2048]

    float *Qb, *KVb, *Ob;
    cudaGetSymbolAddress((void**)&Qb,  g_Q);
    cudaGetSymbolAddress((void**)&KVb, g_KV);
    cudaGetSymbolAddress((void**)&Ob,  g_O);

    // Q and KV projections
    sgemm_nt<<<dim3(QDIM / 128, MTOT / 128), 256>>>(x, wq,  Qb,  MTOT, QDIM,  HIDDEN);
    sgemm_nt<<<dim3(KVDIM / 128, MTOT / 128), 256>>>(x, wkv, KVb, MTOT, KVDIM, HIDDEN);

    // Attention
    cudaFuncSetAttribute(attn_kernel, cudaFuncAttributeMaxDynamicSharedMemorySize, ATTN_SMEM);
    attn_kernel<<<dim3(TT / 64, BB * NH), 256, ATTN_SMEM>>>(Qb, KVb, Ob);

    // Output projection
    sgemm_nt<<<dim3(QDIM / 128, MTOT / 128), 256>>>(Ob, wo, out, MTOT, QDIM, HIDDEN);
}

// round 3
// speedup vs baseline: 1.4181x; 1.4181x over previous
#include <cuda_runtime.h>
#include <cstdint>
#include <math.h>

#define HIDDEN 2048
#define NH 16
#define NKV 4
#define HD 128
#define BB 2
#define TT 2048
#define MTOT (BB*TT)            // 4096 total rows (B*T)
#define QDIM (NH*HD)            // 2048
#define KVDIM (2*NKV*HD)        // 1024

// Scratch (allocation-free)
__device__ float g_Q [MTOT * QDIM];
__device__ float g_KV[MTOT * KVDIM];
__device__ float g_O [MTOT * QDIM];

// ---------------------------------------------------------------------------
// TF32 tensor-core SGEMM: C[M,N] = A[M,K] * B[N,K]^T  (row-major A,B,C)
// BM=BN=128, BK=16, 256 threads = 8 warps (2 m x 4 n), warp tile 64x32.
// mma.sync.m16n8k8.tf32, fragments via ldmatrix from padded smem (stride 20).
// Double-buffered smem (2 x (A+B) x 128x20 words = 40KB).
// ---------------------------------------------------------------------------
#define LDA 20   // words per smem row (16 data + 4 pad; 8-row ldmatrix phase conflict-free)

__device__ __forceinline__ uint32_t f2tf(float f) {
    uint32_t u;
    asm("cvt.rna.tf32.f32 %0, %1;" : "=r"(u) : "f"(f));
    return u;
}

__device__ __forceinline__ void ldsm_x4(uint32_t& r0, uint32_t& r1, uint32_t& r2, uint32_t& r3,
                                        uint32_t addr) {
    asm volatile("ldmatrix.sync.aligned.m8n8.x4.shared.b16 {%0,%1,%2,%3}, [%4];"
                 : "=r"(r0), "=r"(r1), "=r"(r2), "=r"(r3) : "r"(addr));
}

__device__ __forceinline__ void mma_tf32(float& d0, float& d1, float& d2, float& d3,
                                         uint32_t a0, uint32_t a1, uint32_t a2, uint32_t a3,
                                         uint32_t b0, uint32_t b1) {
    asm volatile("mma.sync.aligned.m16n8k8.row.col.f32.tf32.tf32.f32 "
                 "{%0,%1,%2,%3}, {%4,%5,%6,%7}, {%8,%9}, {%0,%1,%2,%3};"
                 : "+f"(d0), "+f"(d1), "+f"(d2), "+f"(d3)
                 : "r"(a0), "r"(a1), "r"(a2), "r"(a3), "r"(b0), "r"(b1));
}

__global__ __launch_bounds__(256, 2) void sgemm_tf32(const float* __restrict__ A,
                                                     const float* __restrict__ B,
                                                     float* __restrict__ C,
                                                     int M, int N, int K)
{
    __shared__ uint32_t sA[2][128 * LDA];
    __shared__ uint32_t sB[2][128 * LDA];

    const int tid  = threadIdx.x;
    const int lane = tid & 31;
    const int wid  = tid >> 5;
    const int wm   = wid & 1;          // 0..1
    const int wn   = wid >> 1;         // 0..3
    const int bm   = blockIdx.y * 128;
    const int bn   = blockIdx.x * 128;

    // global-load mapping: 4 threads per row (16 floats each), 2 row passes
    const int grow = tid >> 2;          // 0..63
    const int gcol = (tid & 3) * 4;     // 0,4,8,12

    // ldmatrix per-thread address components
    const int gA = lane >> 3;                           // which of 4 8x8(b16-pair) matrices
    const int a_row   = (lane & 7) | ((gA & 1) << 3);   // m0,m1: rows 0-7/8-15 @chunk0; m2,m3 @chunk4
    const int a_chunk = (gA >> 1) * 4;
    const int b_row   = (lane & 7) | (((lane >> 3) >> 1) << 3);  // m0,m1: n0-7 chunk0/4; m2,m3: n8-15
    const int b_chunk = ((lane >> 3) & 1) * 4;

    float c[4][4][4];
#pragma unroll
    for (int mi = 0; mi < 4; mi++)
#pragma unroll
        for (int ni = 0; ni < 4; ni++)
#pragma unroll
            for (int r = 0; r < 4; r++) c[mi][ni][r] = 0.f;

    const int NKT = K / 16;

    float4 pa[2], pb[2];

    // prologue: load tile 0
#pragma unroll
    for (int i = 0; i < 2; i++) {
        pa[i] = *(const float4*)(A + (size_t)(bm + grow + 64 * i) * K + gcol);
        pb[i] = *(const float4*)(B + (size_t)(bn + grow + 64 * i) * K + gcol);
    }
    {
        uint4* dA = (uint4*)sA[0];
        uint4* dB = (uint4*)sB[0];
#pragma unroll
        for (int i = 0; i < 2; i++) {
            uint4 ua = make_uint4(f2tf(pa[i].x), f2tf(pa[i].y), f2tf(pa[i].z), f2tf(pa[i].w));
            uint4 ub = make_uint4(f2tf(pb[i].x), f2tf(pb[i].y), f2tf(pb[i].z), f2tf(pb[i].w));
            dA[(grow + 64 * i) * (LDA / 4) + (tid & 3)] = ua;
            dB[(grow + 64 * i) * (LDA / 4) + (tid & 3)] = ub;
        }
    }
    __syncthreads();

    for (int kt = 0; kt < NKT; kt++) {
        const int cur = kt & 1;
        const int k0n = (kt + 1) * 16;

        if (kt + 1 < NKT) {
#pragma unroll
            for (int i = 0; i < 2; i++) {
                pa[i] = *(const float4*)(A + (size_t)(bm + grow + 64 * i) * K + k0n + gcol);
                pb[i] = *(const float4*)(B + (size_t)(bn + grow + 64 * i) * K + k0n + gcol);
            }
        }

        // compute on stage cur
        const uint32_t baseA = (uint32_t)__cvta_generic_to_shared(sA[cur]);
        const uint32_t baseB = (uint32_t)__cvta_generic_to_shared(sB[cur]);
#pragma unroll
        for (int ks = 0; ks < 2; ks++) {
            uint32_t a[4][4];
#pragma unroll
            for (int mi = 0; mi < 4; mi++) {
                uint32_t addr = baseA + 4u * ((wm * 64 + mi * 16 + a_row) * LDA + ks * 8 + a_chunk);
                ldsm_x4(a[mi][0], a[mi][1], a[mi][2], a[mi][3], addr);
            }
            uint32_t b[2][4];
#pragma unroll
            for (int p = 0; p < 2; p++) {
                uint32_t addr = baseB + 4u * ((wn * 32 + p * 16 + b_row) * LDA + ks * 8 + b_chunk);
                ldsm_x4(b[p][0], b[p][1], b[p][2], b[p][3], addr);
            }
#pragma unroll
            for (int mi = 0; mi < 4; mi++) {
#pragma unroll
                for (int p = 0; p < 2; p++) {
                    mma_tf32(c[mi][2*p+0][0], c[mi][2*p+0][1], c[mi][2*p+0][2], c[mi][2*p+0][3],
                             a[mi][0], a[mi][1], a[mi][2], a[mi][3], b[p][0], b[p][1]);
                    mma_tf32(c[mi][2*p+1][0], c[mi][2*p+1][1], c[mi][2*p+1][2], c[mi][2*p+1][3],
                             a[mi][0], a[mi][1], a[mi][2], a[mi][3], b[p][2], b[p][3]);
                }
            }
        }

        if (kt + 1 < NKT) {
            const int nxt = 1 - cur;
            uint4* dA = (uint4*)sA[nxt];
            uint4* dB = (uint4*)sB[nxt];
#pragma unroll
            for (int i = 0; i < 2; i++) {
                uint4 ua = make_uint4(f2tf(pa[i].x), f2tf(pa[i].y), f2tf(pa[i].z), f2tf(pa[i].w));
                uint4 ub = make_uint4(f2tf(pb[i].x), f2tf(pb[i].y), f2tf(pb[i].z), f2tf(pb[i].w));
                dA[(grow + 64 * i) * (LDA / 4) + (tid & 3)] = ua;
                dB[(grow + 64 * i) * (LDA / 4) + (tid & 3)] = ub;
            }
        }
        __syncthreads();
    }

    // epilogue
#pragma unroll
    for (int mi = 0; mi < 4; mi++) {
        int row0 = bm + wm * 64 + mi * 16 + (lane >> 2);
#pragma unroll
        for (int ni = 0; ni < 4; ni++) {
            int col = bn + wn * 32 + ni * 8 + (lane & 3) * 2;
            *(float2*)(C + (size_t)row0 * N + col)       = make_float2(c[mi][ni][0], c[mi][ni][1]);
            *(float2*)(C + (size_t)(row0 + 8) * N + col) = make_float2(c[mi][ni][2], c[mi][ni][3]);
        }
    }
}

// ---------------------------------------------------------------------------
// Flash attention (causal, GQA) — unchanged fp32 version from round 1.
// ---------------------------------------------------------------------------
#define QS_STRIDE 132
#define KS_STRIDE 136
#define VS_STRIDE 132
#define PS_STRIDE 65
#define ATTN_SMEM ((64*(QS_STRIDE+KS_STRIDE+VS_STRIDE+PS_STRIDE))*4)

__global__ __launch_bounds__(256) void attn_kernel(const float* __restrict__ Q,
                                                   const float* __restrict__ KV,
                                                   float* __restrict__ O)
{
    extern __shared__ float smf[];
    float* Qs = smf;
    float* Ks = Qs + 64 * QS_STRIDE;
    float* Vs = Ks + 64 * KS_STRIDE;
    float* Ps = Vs + 64 * VS_STRIDE;

    const int bh  = blockIdx.y;
    const int b   = bh / NH;
    const int h   = bh % NH;
    const int kvh = h / (NH / NKV);
    const int qm  = blockIdx.x * 64;

    const int tid  = threadIdx.x;
    const int w    = tid >> 5;
    const int lane = tid & 31;
    const int r_in = lane >> 2;
    const int cg   = lane & 3;
    const int row  = w * 8 + r_in;
    const int qrow = qm + row;

    for (int i = tid; i < 64 * 32; i += 256) {
        int r = i >> 5, c4 = i & 31;
        float4 v = *(const float4*)(Q + (size_t)(b * TT + qm + r) * QDIM + h * HD + c4 * 4);
        *(float4*)(Qs + r * QS_STRIDE + c4 * 4) = v;
    }

    float m_old = -INFINITY, l = 0.f;
    float acc[32];
#pragma unroll
    for (int i = 0; i < 32; i++) acc[i] = 0.f;

    const float scale = 0.08838834764831845f;
    const float* Kbase = KV + (size_t)b * TT * KVDIM + kvh * HD;
    const int ntiles = qm / 64 + 1;

    for (int t = 0; t < ntiles; t++) {
        const int n0 = t * 64;
        __syncthreads();
        for (int i = tid; i < 64 * 32; i += 256) {
            int r = i >> 5, c4 = i & 31;
            const float* src = Kbase + (size_t)(n0 + r) * KVDIM + c4 * 4;
            *(float4*)(Ks + r * KS_STRIDE + c4 * 4) = *(const float4*)src;
            *(float4*)(Vs + r * VS_STRIDE + c4 * 4) = *(const float4*)(src + NKV * HD);
        }
        __syncthreads();

        float s[16];
#pragma unroll
        for (int j = 0; j < 16; j++) s[j] = 0.f;
#pragma unroll 8
        for (int dc = 0; dc < 32; dc++) {
            float4 q4 = *(float4*)(Qs + row * QS_STRIDE + dc * 4);
#pragma unroll
            for (int j = 0; j < 16; j++) {
                float4 k4 = *(float4*)(Ks + (cg + 4 * j) * KS_STRIDE + dc * 4);
                s[j] += q4.x * k4.x + q4.y * k4.y + q4.z * k4.z + q4.w * k4.w;
            }
        }

#pragma unroll
        for (int j = 0; j < 16; j++) {
            int kcol = n0 + cg + 4 * j;
            s[j] = (kcol <= qrow) ? s[j] * scale : -INFINITY;
        }

        float mt = s[0];
#pragma unroll
        for (int j = 1; j < 16; j++) mt = fmaxf(mt, s[j]);
        mt = fmaxf(mt, __shfl_xor_sync(0xffffffffu, mt, 1));
        mt = fmaxf(mt, __shfl_xor_sync(0xffffffffu, mt, 2));
        float m_new = fmaxf(m_old, mt);
        float alpha = __expf(m_old - m_new);
        float ls = 0.f;
#pragma unroll
        for (int j = 0; j < 16; j++) {
            float p = __expf(s[j] - m_new);
            s[j] = p;
            ls += p;
        }
        ls += __shfl_xor_sync(0xffffffffu, ls, 1);
        ls += __shfl_xor_sync(0xffffffffu, ls, 2);
        l = l * alpha + ls;
        m_old = m_new;

#pragma unroll
        for (int j = 0; j < 16; j++) Ps[row * PS_STRIDE + cg + 4 * j] = s[j];
        __syncwarp();

#pragma unroll
        for (int i = 0; i < 32; i++) acc[i] *= alpha;
        for (int cix = 0; cix < 64; cix++) {
            float p = Ps[row * PS_STRIDE + cix];
#pragma unroll
            for (int i = 0; i < 8; i++) {
                float4 v4 = *(float4*)(Vs + cix * VS_STRIDE + (cg + 4 * i) * 4);
                acc[i * 4 + 0] += p * v4.x;
                acc[i * 4 + 1] += p * v4.y;
                acc[i * 4 + 2] += p * v4.z;
                acc[i * 4 + 3] += p * v4.w;
            }
        }
    }

    const float inv_l = 1.f / l;
    float* Op = O + (size_t)(b * TT + qm + row) * QDIM + h * HD;
#pragma unroll
    for (int i = 0; i < 8; i++) {
        float4 v = make_float4(acc[i * 4 + 0] * inv_l, acc[i * 4 + 1] * inv_l,
                               acc[i * 4 + 2] * inv_l, acc[i * 4 + 3] * inv_l);
        *(float4*)(Op + (cg + 4 * i) * 4) = v;
    }
}

// ---------------------------------------------------------------------------

extern "C" void kernel_launch(void* const* d_in, const int* in_sizes, int n_in,
                              void* d_out, int out_size)
{
    const float* x   = (const float*)d_in[0];
    const float* wq  = (const float*)d_in[1];
    const float* wkv = (const float*)d_in[2];
    const float* wo  = (const float*)d_in[3];
    float* out = (float*)d_out;

    float *Qb, *KVb, *Ob;
    cudaGetSymbolAddress((void**)&Qb,  g_Q);
    cudaGetSymbolAddress((void**)&KVb, g_KV);
    cudaGetSymbolAddress((void**)&Ob,  g_O);

    sgemm_tf32<<<dim3(QDIM / 128, MTOT / 128), 256>>>(x, wq,  Qb,  MTOT, QDIM,  HIDDEN);
    sgemm_tf32<<<dim3(KVDIM / 128, MTOT / 128), 256>>>(x, wkv, KVb, MTOT, KVDIM, HIDDEN);

    cudaFuncSetAttribute(attn_kernel, cudaFuncAttributeMaxDynamicSharedMemorySize, ATTN_SMEM);
    attn_kernel<<<dim3(TT / 64, BB * NH), 256, ATTN_SMEM>>>(Qb, KVb, Ob);

    sgemm_tf32<<<dim3(QDIM / 128, MTOT / 128), 256>>>(Ob, wo, out, MTOT, QDIM, HIDDEN);
}

// round 4
// speedup vs baseline: 4.0830x; 2.8793x over previous
#include <cuda_runtime.h>
#include <cstdint>
#include <math.h>

#define HIDDEN 2048
#define NH 16
#define NKV 4
#define HD 128
#define BB 2
#define TT 2048
#define MTOT (BB*TT)            // 4096 rows (B*T)
#define QDIM (NH*HD)            // 2048
#define KVDIM (2*NKV*HD)        // 1024

// Scratch (allocation-free)
__device__ float g_Q [MTOT * QDIM];
__device__ float g_KV[MTOT * KVDIM];
__device__ float g_O [MTOT * QDIM];

__device__ __forceinline__ uint32_t f2tf(float f) {
    uint32_t u;
    asm("cvt.rna.tf32.f32 %0, %1;" : "=r"(u) : "f"(f));
    return u;
}

__device__ __forceinline__ void ldsm_x4(uint32_t& r0, uint32_t& r1, uint32_t& r2, uint32_t& r3,
                                        uint32_t addr) {
    asm volatile("ldmatrix.sync.aligned.m8n8.x4.shared.b16 {%0,%1,%2,%3}, [%4];"
                 : "=r"(r0), "=r"(r1), "=r"(r2), "=r"(r3) : "r"(addr));
}

__device__ __forceinline__ void mma_tf32(float& d0, float& d1, float& d2, float& d3,
                                         uint32_t a0, uint32_t a1, uint32_t a2, uint32_t a3,
                                         uint32_t b0, uint32_t b1) {
    asm volatile("mma.sync.aligned.m16n8k8.row.col.f32.tf32.tf32.f32 "
                 "{%0,%1,%2,%3}, {%4,%5,%6,%7}, {%8,%9}, {%0,%1,%2,%3};"
                 : "+f"(d0), "+f"(d1), "+f"(d2), "+f"(d3)
                 : "r"(a0), "r"(a1), "r"(a2), "r"(a3), "r"(b0), "r"(b1));
}

__device__ __forceinline__ void mma_tf32a(float* d, const uint32_t* a, uint32_t b0, uint32_t b1) {
    mma_tf32(d[0], d[1], d[2], d[3], a[0], a[1], a[2], a[3], b0, b1);
}

// ---------------------------------------------------------------------------
// TF32 tensor-core SGEMM (unchanged from round 3): C[M,N] = A[M,K] * B[N,K]^T
// ---------------------------------------------------------------------------
#define LDA 20

__global__ __launch_bounds__(256, 2) void sgemm_tf32(const float* __restrict__ A,
                                                     const float* __restrict__ B,
                                                     float* __restrict__ C,
                                                     int M, int N, int K)
{
    __shared__ uint32_t sA[2][128 * LDA];
    __shared__ uint32_t sB[2][128 * LDA];

    const int tid  = threadIdx.x;
    const int lane = tid & 31;
    const int wid  = tid >> 5;
    const int wm   = wid & 1;
    const int wn   = wid >> 1;
    const int bm   = blockIdx.y * 128;
    const int bn   = blockIdx.x * 128;

    const int grow = tid >> 2;
    const int gcol = (tid & 3) * 4;

    const int gA = lane >> 3;
    const int a_row   = (lane & 7) | ((gA & 1) << 3);
    const int a_chunk = (gA >> 1) * 4;
    const int b_row   = (lane & 7) | (((lane >> 3) >> 1) << 3);
    const int b_chunk = ((lane >> 3) & 1) * 4;

    float c[4][4][4];
#pragma unroll
    for (int mi = 0; mi < 4; mi++)
#pragma unroll
        for (int ni = 0; ni < 4; ni++)
#pragma unroll
            for (int r = 0; r < 4; r++) c[mi][ni][r] = 0.f;

    const int NKT = K / 16;
    float4 pa[2], pb[2];

#pragma unroll
    for (int i = 0; i < 2; i++) {
        pa[i] = *(const float4*)(A + (size_t)(bm + grow + 64 * i) * K + gcol);
        pb[i] = *(const float4*)(B + (size_t)(bn + grow + 64 * i) * K + gcol);
    }
    {
        uint4* dA = (uint4*)sA[0];
        uint4* dB = (uint4*)sB[0];
#pragma unroll
        for (int i = 0; i < 2; i++) {
            uint4 ua = make_uint4(f2tf(pa[i].x), f2tf(pa[i].y), f2tf(pa[i].z), f2tf(pa[i].w));
            uint4 ub = make_uint4(f2tf(pb[i].x), f2tf(pb[i].y), f2tf(pb[i].z), f2tf(pb[i].w));
            dA[(grow + 64 * i) * (LDA / 4) + (tid & 3)] = ua;
            dB[(grow + 64 * i) * (LDA / 4) + (tid & 3)] = ub;
        }
    }
    __syncthreads();

    for (int kt = 0; kt < NKT; kt++) {
        const int cur = kt & 1;
        const int k0n = (kt + 1) * 16;

        if (kt + 1 < NKT) {
#pragma unroll
            for (int i = 0; i < 2; i++) {
                pa[i] = *(const float4*)(A + (size_t)(bm + grow + 64 * i) * K + k0n + gcol);
                pb[i] = *(const float4*)(B + (size_t)(bn + grow + 64 * i) * K + k0n + gcol);
            }
        }

        const uint32_t baseA = (uint32_t)__cvta_generic_to_shared(sA[cur]);
        const uint32_t baseB = (uint32_t)__cvta_generic_to_shared(sB[cur]);
#pragma unroll
        for (int ks = 0; ks < 2; ks++) {
            uint32_t a[4][4];
#pragma unroll
            for (int mi = 0; mi < 4; mi++) {
                uint32_t addr = baseA + 4u * ((wm * 64 + mi * 16 + a_row) * LDA + ks * 8 + a_chunk);
                ldsm_x4(a[mi][0], a[mi][1], a[mi][2], a[mi][3], addr);
            }
            uint32_t b[2][4];
#pragma unroll
            for (int p = 0; p < 2; p++) {
                uint32_t addr = baseB + 4u * ((wn * 32 + p * 16 + b_row) * LDA + ks * 8 + b_chunk);
                ldsm_x4(b[p][0], b[p][1], b[p][2], b[p][3], addr);
            }
#pragma unroll
            for (int mi = 0; mi < 4; mi++) {
#pragma unroll
                for (int p = 0; p < 2; p++) {
                    mma_tf32a(c[mi][2*p+0], a[mi], b[p][0], b[p][1]);
                    mma_tf32a(c[mi][2*p+1], a[mi], b[p][2], b[p][3]);
                }
            }
        }

        if (kt + 1 < NKT) {
            const int nxt = 1 - cur;
            uint4* dA = (uint4*)sA[nxt];
            uint4* dB = (uint4*)sB[nxt];
#pragma unroll
            for (int i = 0; i < 2; i++) {
                uint4 ua = make_uint4(f2tf(pa[i].x), f2tf(pa[i].y), f2tf(pa[i].z), f2tf(pa[i].w));
                uint4 ub = make_uint4(f2tf(pb[i].x), f2tf(pb[i].y), f2tf(pb[i].z), f2tf(pb[i].w));
                dA[(grow + 64 * i) * (LDA / 4) + (tid & 3)] = ua;
                dB[(grow + 64 * i) * (LDA / 4) + (tid & 3)] = ub;
            }
        }
        __syncthreads();
    }

#pragma unroll
    for (int mi = 0; mi < 4; mi++) {
        int row0 = bm + wm * 64 + mi * 16 + (lane >> 2);
#pragma unroll
        for (int ni = 0; ni < 4; ni++) {
            int col = bn + wn * 32 + ni * 8 + (lane & 3) * 2;
            *(float2*)(C + (size_t)row0 * N + col)       = make_float2(c[mi][ni][0], c[mi][ni][1]);
            *(float2*)(C + (size_t)(row0 + 8) * N + col) = make_float2(c[mi][ni][2], c[mi][ni][3]);
        }
    }
}

// ---------------------------------------------------------------------------
// Tensor-core flash attention (causal, GQA), tf32 mma.
// BLOCK_M=64 (4 warps x 16 rows), BLOCK_N=64, D=128. 128 threads, 2 CTAs/SM.
// Q resident in registers as A-fragments; K in smem [64][132];
// V transposed in smem [128][68]; P converted C-frag->A-frag via quad shuffles.
// ---------------------------------------------------------------------------
#define KS_STR 132   // words per K row  (33 float4, odd -> conflict-free ldmatrix)
#define VT_STR 68    // words per Vt row (17 float4, odd)
#define ATTN_SMEM ((64*KS_STR + 128*VT_STR) * 4)   // 68608 B

__global__ __launch_bounds__(128, 2) void attn_mma(const float* __restrict__ Q,
                                                   const float* __restrict__ KV,
                                                   float* __restrict__ O)
{
    extern __shared__ uint32_t smu[];
    uint32_t* sK = smu;               // [64][132] tf32
    uint32_t* sV = smu + 64 * KS_STR; // [128][68]  tf32 (V transposed: [d][key])

    const int bh  = blockIdx.y;
    const int b   = bh / NH;
    const int h   = bh % NH;
    const int kvh = h / (NH / NKV);
    const int qm  = (int)(gridDim.x - 1 - blockIdx.x) * 64;   // heavy tiles first

    const int tid  = threadIdx.x;
    const int w    = tid >> 5;
    const int lane = tid & 31;
    const int g    = lane >> 3;
    const int q4   = lane & 3;
    const int hr   = lane >> 2;                       // 0..7
    const int b_row   = (lane & 7) | ((g >> 1) << 3); // B-operand ldmatrix row
    const int b_chunk = (g & 1) * 4;                  // B-operand word offset

    const int r0 = qm + 16 * w + hr;   // global query rows owned by this thread
    const int r1 = r0 + 8;

    // Q fragments: pre-scaled, tf32. a0=(r0,q4) a1=(r1,q4) a2=(r0,q4+4) a3=(r1,q4+4)
    const float scale = 0.08838834764831845f;   // 1/sqrt(128)
    uint32_t qf[16][4];
    {
        const float* Q0 = Q + ((size_t)(b * TT) + r0) * QDIM + h * HD;
        const float* Q1 = Q + ((size_t)(b * TT) + r1) * QDIM + h * HD;
#pragma unroll
        for (int ks = 0; ks < 16; ks++) {
            qf[ks][0] = f2tf(scale * Q0[8 * ks + q4]);
            qf[ks][1] = f2tf(scale * Q1[8 * ks + q4]);
            qf[ks][2] = f2tf(scale * Q0[8 * ks + q4 + 4]);
            qf[ks][3] = f2tf(scale * Q1[8 * ks + q4 + 4]);
        }
    }

    float o[16][4];
#pragma unroll
    for (int i = 0; i < 16; i++)
#pragma unroll
        for (int r = 0; r < 4; r++) o[i][r] = 0.f;
    float m0 = -INFINITY, m1 = -INFINITY, l0 = 0.f, l1 = 0.f;

    const float* Kg = KV + (size_t)b * TT * KVDIM + kvh * HD;
    const float* Vg = Kg + NKV * HD;

    const uint32_t sKb = (uint32_t)__cvta_generic_to_shared(sK);
    const uint32_t sVb = (uint32_t)__cvta_generic_to_shared(sV);
    const int lo_src = (lane & 28) + (q4 >> 1);
    const bool sel_odd = (q4 & 1);

    const int ntiles = qm / 64 + 1;
    for (int t = 0; t < ntiles; t++) {
        const int n0 = t * 64;
        __syncthreads();   // previous tile's compute done reading sK/sV

        // K tile -> sK (coalesced, tf32 on store)
        for (int i = tid; i < 2048; i += 128) {
            int r = i >> 5, c4 = i & 31;
            float4 v = *(const float4*)(Kg + (size_t)(n0 + r) * KVDIM + c4 * 4);
            ((uint4*)sK)[r * (KS_STR / 4) + c4] =
                make_uint4(f2tf(v.x), f2tf(v.y), f2tf(v.z), f2tf(v.w));
        }
        // V tile -> sV transposed: lanes across keys (conflict-free STS)
        for (int i = tid; i < 2048; i += 128) {
            int key = i & 63, c4 = i >> 6;
            float4 v = *(const float4*)(Vg + (size_t)(n0 + key) * KVDIM + c4 * 4);
            sV[(c4 * 4 + 0) * VT_STR + key] = f2tf(v.x);
            sV[(c4 * 4 + 1) * VT_STR + key] = f2tf(v.y);
            sV[(c4 * 4 + 2) * VT_STR + key] = f2tf(v.z);
            sV[(c4 * 4 + 3) * VT_STR + key] = f2tf(v.w);
        }
        __syncthreads();

        // S = Q K^T  (16 k-steps over D)
        float s[8][4];
#pragma unroll
        for (int j = 0; j < 8; j++)
#pragma unroll
            for (int r = 0; r < 4; r++) s[j][r] = 0.f;
#pragma unroll
        for (int ks = 0; ks < 16; ks++) {
            uint32_t kb[4][4];
#pragma unroll
            for (int jj = 0; jj < 4; jj++) {
                uint32_t addr = sKb + 4u * ((16 * jj + b_row) * KS_STR + 8 * ks + b_chunk);
                ldsm_x4(kb[jj][0], kb[jj][1], kb[jj][2], kb[jj][3], addr);
            }
#pragma unroll
            for (int jj = 0; jj < 4; jj++) {
                mma_tf32a(s[2 * jj + 0], qf[ks], kb[jj][0], kb[jj][1]);
                mma_tf32a(s[2 * jj + 1], qf[ks], kb[jj][2], kb[jj][3]);
            }
        }

        // causal mask + online softmax (C-frag rows r0,r1; cols n0+8j+2q4,+1)
        float mt0 = -INFINITY, mt1 = -INFINITY;
#pragma unroll
        for (int j = 0; j < 8; j++) {
            int c0 = n0 + 8 * j + 2 * q4, c1 = c0 + 1;
            if (c0 > r0) s[j][0] = -1e30f;
            if (c1 > r0) s[j][1] = -1e30f;
            if (c0 > r1) s[j][2] = -1e30f;
            if (c1 > r1) s[j][3] = -1e30f;
            mt0 = fmaxf(mt0, fmaxf(s[j][0], s[j][1]));
            mt1 = fmaxf(mt1, fmaxf(s[j][2], s[j][3]));
        }
        mt0 = fmaxf(mt0, __shfl_xor_sync(0xffffffffu, mt0, 1));
        mt0 = fmaxf(mt0, __shfl_xor_sync(0xffffffffu, mt0, 2));
        mt1 = fmaxf(mt1, __shfl_xor_sync(0xffffffffu, mt1, 1));
        mt1 = fmaxf(mt1, __shfl_xor_sync(0xffffffffu, mt1, 2));
        float mn0 = fmaxf(m0, mt0), mn1 = fmaxf(m1, mt1);
        float al0 = __expf(m0 - mn0), al1 = __expf(m1 - mn1);
        m0 = mn0; m1 = mn1;
        float ls0 = 0.f, ls1 = 0.f;
#pragma unroll
        for (int j = 0; j < 8; j++) {
            s[j][0] = __expf(s[j][0] - mn0); ls0 += s[j][0];
            s[j][1] = __expf(s[j][1] - mn0); ls0 += s[j][1];
            s[j][2] = __expf(s[j][2] - mn1); ls1 += s[j][2];
            s[j][3] = __expf(s[j][3] - mn1); ls1 += s[j][3];
        }
        l0 = l0 * al0 + ls0;
        l1 = l1 * al1 + ls1;
#pragma unroll
        for (int i = 0; i < 16; i++) {
            o[i][0] *= al0; o[i][1] *= al0;
            o[i][2] *= al1; o[i][3] *= al1;
        }

        // O += P V : per k-step (8 keys), convert P C-frag -> A-frag via quad shfl
#pragma unroll
        for (int ks = 0; ks < 8; ks++) {
            float v00 = __shfl_sync(0xffffffffu, s[ks][0], lo_src);
            float v01 = __shfl_sync(0xffffffffu, s[ks][1], lo_src);
            float v02 = __shfl_sync(0xffffffffu, s[ks][2], lo_src);
            float v03 = __shfl_sync(0xffffffffu, s[ks][3], lo_src);
            float w00 = __shfl_sync(0xffffffffu, s[ks][0], lo_src + 2);
            float w01 = __shfl_sync(0xffffffffu, s[ks][1], lo_src + 2);
            float w02 = __shfl_sync(0xffffffffu, s[ks][2], lo_src + 2);
            float w03 = __shfl_sync(0xffffffffu, s[ks][3], lo_src + 2);
            uint32_t pa[4];
            pa[0] = f2tf(sel_odd ? v01 : v00);   // P(r0, q4)
            pa[1] = f2tf(sel_odd ? v03 : v02);   // P(r1, q4)
            pa[2] = f2tf(sel_odd ? w01 : w00);   // P(r0, q4+4)
            pa[3] = f2tf(sel_odd ? w03 : w02);   // P(r1, q4+4)
#pragma unroll
            for (int dd = 0; dd < 8; dd++) {
                uint32_t vb0, vb1, vb2, vb3;
                uint32_t addr = sVb + 4u * ((16 * dd + b_row) * VT_STR + 8 * ks + b_chunk);
                ldsm_x4(vb0, vb1, vb2, vb3, addr);
                mma_tf32a(o[2 * dd + 0], pa, vb0, vb1);
                mma_tf32a(o[2 * dd + 1], pa, vb2, vb3);
            }
        }
    }

    // epilogue: reduce l across quad, normalize, store
    l0 += __shfl_xor_sync(0xffffffffu, l0, 1);
    l0 += __shfl_xor_sync(0xffffffffu, l0, 2);
    l1 += __shfl_xor_sync(0xffffffffu, l1, 1);
    l1 += __shfl_xor_sync(0xffffffffu, l1, 2);
    const float i0 = 1.f / l0, i1 = 1.f / l1;

    float* O0 = O + ((size_t)(b * TT) + r0) * QDIM + h * HD;
    float* O1 = O + ((size_t)(b * TT) + r1) * QDIM + h * HD;
#pragma unroll
    for (int dd = 0; dd < 16; dd++) {
        *(float2*)(O0 + 8 * dd + 2 * q4) = make_float2(o[dd][0] * i0, o[dd][1] * i0);
        *(float2*)(O1 + 8 * dd + 2 * q4) = make_float2(o[dd][2] * i1, o[dd][3] * i1);
    }
}

// ---------------------------------------------------------------------------

extern "C" void kernel_launch(void* const* d_in, const int* in_sizes, int n_in,
                              void* d_out, int out_size)
{
    const float* x   = (const float*)d_in[0];
    const float* wq  = (const float*)d_in[1];
    const float* wkv = (const float*)d_in[2];
    const float* wo  = (const float*)d_in[3];
    float* out = (float*)d_out;

    float *Qb, *KVb, *Ob;
    cudaGetSymbolAddress((void**)&Qb,  g_Q);
    cudaGetSymbolAddress((void**)&KVb, g_KV);
    cudaGetSymbolAddress((void**)&Ob,  g_O);

    sgemm_tf32<<<dim3(QDIM / 128, MTOT / 128), 256>>>(x, wq,  Qb,  MTOT, QDIM,  HIDDEN);
    sgemm_tf32<<<dim3(KVDIM / 128, MTOT / 128), 256>>>(x, wkv, KVb, MTOT, KVDIM, HIDDEN);

    cudaFuncSetAttribute(attn_mma, cudaFuncAttributeMaxDynamicSharedMemorySize, ATTN_SMEM);
    attn_mma<<<dim3(TT / 64, BB * NH), 128, ATTN_SMEM>>>(Qb, KVb, Ob);

    sgemm_tf32<<<dim3(QDIM / 128, MTOT / 128), 256>>>(Ob, wo, out, MTOT, QDIM, HIDDEN);
}

// round 6
// speedup vs baseline: 4.1595x; 1.0187x over previous
#include <cuda_runtime.h>
#include <cstdint>
#include <math.h>

#define HIDDEN 2048
#define NH 16
#define NKV 4
#define HD 128
#define BB 2
#define TT 2048
#define MTOT (BB*TT)            // 4096 rows (B*T)
#define QDIM (NH*HD)            // 2048
#define KVDIM (2*NKV*HD)        // 1024

// Scratch (allocation-free)
__device__ float g_Q  [MTOT * QDIM];     // Q projection out (fp32)
__device__ float g_KV [MTOT * KVDIM];    // KV projection out (fp32)
__device__ float g_O  [MTOT * QDIM];     // attention out (tf32-rounded fp32)
__device__ float g_xt [MTOT * HIDDEN];   // tf32-rounded inputs
__device__ float g_wqt [QDIM * HIDDEN];
__device__ float g_wkvt[KVDIM * HIDDEN];
__device__ float g_wot [HIDDEN * QDIM];

__device__ __forceinline__ uint32_t f2tf(float f) {
    uint32_t u;
    asm("cvt.rna.tf32.f32 %0, %1;" : "=r"(u) : "f"(f));
    return u;
}

__device__ __forceinline__ void ldsm_x4(uint32_t& r0, uint32_t& r1, uint32_t& r2, uint32_t& r3,
                                        uint32_t addr) {
    asm volatile("ldmatrix.sync.aligned.m8n8.x4.shared.b16 {%0,%1,%2,%3}, [%4];"
                 : "=r"(r0), "=r"(r1), "=r"(r2), "=r"(r3) : "r"(addr));
}

__device__ __forceinline__ void mma_tf32(float& d0, float& d1, float& d2, float& d3,
                                         uint32_t a0, uint32_t a1, uint32_t a2, uint32_t a3,
                                         uint32_t b0, uint32_t b1) {
    asm volatile("mma.sync.aligned.m16n8k8.row.col.f32.tf32.tf32.f32 "
                 "{%0,%1,%2,%3}, {%4,%5,%6,%7}, {%8,%9}, {%0,%1,%2,%3};"
                 : "+f"(d0), "+f"(d1), "+f"(d2), "+f"(d3)
                 : "r"(a0), "r"(a1), "r"(a2), "r"(a3), "r"(b0), "r"(b1));
}

__device__ __forceinline__ void mma_tf32a(float* d, const uint32_t* a, uint32_t b0, uint32_t b1) {
    mma_tf32(d[0], d[1], d[2], d[3], a[0], a[1], a[2], a[3], b0, b1);
}

__device__ __forceinline__ void cp16(uint32_t smaddr, const void* g) {
    asm volatile("cp.async.cg.shared.global [%0], [%1], 16;" :: "r"(smaddr), "l"(g));
}

// ---------------------------------------------------------------------------
// Elementwise tf32-rounding pass (vectorized)
// ---------------------------------------------------------------------------
__global__ void cvt_tf32_k(const float4* __restrict__ in, float4* __restrict__ out, int n4)
{
    int i = blockIdx.x * blockDim.x + threadIdx.x;
    if (i < n4) {
        float4 v = in[i];
        out[i] = make_float4(__uint_as_float(f2tf(v.x)), __uint_as_float(f2tf(v.y)),
                             __uint_as_float(f2tf(v.z)), __uint_as_float(f2tf(v.w)));
    }
}

// ---------------------------------------------------------------------------
// TF32 GEMM core with cp.async 4-stage pipeline.
// Inputs must be pre-rounded to tf32 (raw bits consumed by mma).
// C[bm:bm+128, bn:bn+128] = A[.,K] * B[.,K]^T ; 256 threads, 8 warps (2x4).
// ---------------------------------------------------------------------------
#define LDA 20
#define NSTAGE 4
#define STG_W (128 * LDA)
#define GEMM_SMEM (NSTAGE * 2 * STG_W * 4)   // 81920 B

__device__ __forceinline__ void gemm_core(const float* __restrict__ A,
                                          const float* __restrict__ B,
                                          float* __restrict__ C,
                                          int bm, int bn, int N, int K)
{
    extern __shared__ uint32_t smg[];
    uint32_t* sA = smg;
    uint32_t* sB = smg + NSTAGE * STG_W;

    const int tid  = threadIdx.x;
    const int lane = tid & 31;
    const int wid  = tid >> 5;
    const int wm   = wid & 1;
    const int wn   = wid >> 1;

    const int grow  = tid >> 2;       // 0..63
    const int gcol4 = tid & 3;        // 16B chunk 0..3

    const int gA = lane >> 3;
    const int a_row   = (lane & 7) | ((gA & 1) << 3);
    const int a_chunk = (gA >> 1) * 4;
    const int b_row   = (lane & 7) | (((lane >> 3) >> 1) << 3);
    const int b_chunk = ((lane >> 3) & 1) * 4;

    const uint32_t sAb = (uint32_t)__cvta_generic_to_shared(sA);
    const uint32_t sBb = (uint32_t)__cvta_generic_to_shared(sB);

    const float* Ar = A + (size_t)(bm + grow) * K + gcol4 * 4;
    const float* Br = B + (size_t)(bn + grow) * K + gcol4 * 4;
    const uint32_t doff = 4u * (grow * LDA + gcol4 * 4);

    float c[4][4][4];
#pragma unroll
    for (int mi = 0; mi < 4; mi++)
#pragma unroll
        for (int ni = 0; ni < 4; ni++)
#pragma unroll
            for (int r = 0; r < 4; r++) c[mi][ni][r] = 0.f;

    const int NKT = K / 16;

    auto issue = [&](int kt) {
        const int s = kt & (NSTAGE - 1);
        const uint32_t sb = 4u * (s * STG_W);
        const int koff = kt * 16;
        cp16(sAb + sb + doff,                 Ar + koff);
        cp16(sAb + sb + doff + 4u * 64 * LDA, Ar + koff + (size_t)64 * K);
        cp16(sBb + sb + doff,                 Br + koff);
        cp16(sBb + sb + doff + 4u * 64 * LDA, Br + koff + (size_t)64 * K);
    };

    issue(0); asm volatile("cp.async.commit_group;" ::: "memory");
    issue(1); asm volatile("cp.async.commit_group;" ::: "memory");
    issue(2); asm volatile("cp.async.commit_group;" ::: "memory");

    for (int kt = 0; kt < NKT; kt++) {
        asm volatile("cp.async.wait_group 2;" ::: "memory");
        __syncthreads();

        if (kt + 3 < NKT) issue(kt + 3);
        asm volatile("cp.async.commit_group;" ::: "memory");

        const int cur = kt & (NSTAGE - 1);
        const uint32_t baseA = sAb + 4u * (cur * STG_W);
        const uint32_t baseB = sBb + 4u * (cur * STG_W);
#pragma unroll
        for (int ks = 0; ks < 2; ks++) {
            uint32_t a[4][4];
#pragma unroll
            for (int mi = 0; mi < 4; mi++) {
                uint32_t addr = baseA + 4u * ((wm * 64 + mi * 16 + a_row) * LDA + ks * 8 + a_chunk);
                ldsm_x4(a[mi][0], a[mi][1], a[mi][2], a[mi][3], addr);
            }
            uint32_t b[2][4];
#pragma unroll
            for (int p = 0; p < 2; p++) {
                uint32_t addr = baseB + 4u * ((wn * 32 + p * 16 + b_row) * LDA + ks * 8 + b_chunk);
                ldsm_x4(b[p][0], b[p][1], b[p][2], b[p][3], addr);
            }
#pragma unroll
            for (int mi = 0; mi < 4; mi++) {
#pragma unroll
                for (int p = 0; p < 2; p++) {
                    mma_tf32a(c[mi][2*p+0], a[mi], b[p][0], b[p][1]);
                    mma_tf32a(c[mi][2*p+1], a[mi], b[p][2], b[p][3]);
                }
            }
        }
    }

#pragma unroll
    for (int mi = 0; mi < 4; mi++) {
        int row0 = bm + wm * 64 + mi * 16 + (lane >> 2);
#pragma unroll
        for (int ni = 0; ni < 4; ni++) {
            int col = bn + wn * 32 + ni * 8 + (lane & 3) * 2;
            *(float2*)(C + (size_t)row0 * N + col)       = make_float2(c[mi][ni][0], c[mi][ni][1]);
            *(float2*)(C + (size_t)(row0 + 8) * N + col) = make_float2(c[mi][ni][2], c[mi][ni][3]);
        }
    }
}

// Fused Q + KV projection: grid.x = 16 (Q cols) + 8 (KV cols), grid.y = 32 (rows)
__global__ __launch_bounds__(256, 2) void gemm_qkv(const float* __restrict__ xt,
                                                   const float* __restrict__ wqt,
                                                   const float* __restrict__ wkvt,
                                                   float* __restrict__ Qo,
                                                   float* __restrict__ KVo)
{
    const int bx = blockIdx.x;
    const int bm = blockIdx.y * 128;
    if (bx < QDIM / 128)
        gemm_core(xt, wqt, Qo, bm, bx * 128, QDIM, HIDDEN);
    else
        gemm_core(xt, wkvt, KVo, bm, (bx - QDIM / 128) * 128, KVDIM, HIDDEN);
}

__global__ __launch_bounds__(256, 2) void gemm_o(const float* __restrict__ A,
                                                 const float* __restrict__ B,
                                                 float* __restrict__ C)
{
    gemm_core(A, B, C, blockIdx.y * 128, blockIdx.x * 128, QDIM, HIDDEN);
}

// ---------------------------------------------------------------------------
// Tensor-core flash attention (causal, GQA), tf32 mma — unchanged from R4
// except the epilogue stores tf32-rounded values (feeds O-projection directly).
// ---------------------------------------------------------------------------
#define KS_STR 132
#define VT_STR 68
#define ATTN_SMEM ((64*KS_STR + 128*VT_STR) * 4)

__global__ __launch_bounds__(128, 2) void attn_mma(const float* __restrict__ Q,
                                                   const float* __restrict__ KV,
                                                   float* __restrict__ O)
{
    extern __shared__ uint32_t smu[];
    uint32_t* sK = smu;
    uint32_t* sV = smu + 64 * KS_STR;

    const int bh  = blockIdx.y;
    const int b   = bh / NH;
    const int h   = bh % NH;
    const int kvh = h / (NH / NKV);
    const int qm  = (int)(gridDim.x - 1 - blockIdx.x) * 64;

    const int tid  = threadIdx.x;
    const int w    = tid >> 5;
    const int lane = tid & 31;
    const int g    = lane >> 3;
    const int q4   = lane & 3;
    const int hr   = lane >> 2;
    const int b_row   = (lane & 7) | ((g >> 1) << 3);
    const int b_chunk = (g & 1) * 4;

    const int r0 = qm + 16 * w + hr;
    const int r1 = r0 + 8;

    const float scale = 0.08838834764831845f;
    uint32_t qf[16][4];
    {
        const float* Q0 = Q + ((size_t)(b * TT) + r0) * QDIM + h * HD;
        const float* Q1 = Q + ((size_t)(b * TT) + r1) * QDIM + h * HD;
#pragma unroll
        for (int ks = 0; ks < 16; ks++) {
            qf[ks][0] = f2tf(scale * Q0[8 * ks + q4]);
            qf[ks][1] = f2tf(scale * Q1[8 * ks + q4]);
            qf[ks][2] = f2tf(scale * Q0[8 * ks + q4 + 4]);
            qf[ks][3] = f2tf(scale * Q1[8 * ks + q4 + 4]);
        }
    }

    float o[16][4];
#pragma unroll
    for (int i = 0; i < 16; i++)
#pragma unroll
        for (int r = 0; r < 4; r++) o[i][r] = 0.f;
    float m0 = -INFINITY, m1 = -INFINITY, l0 = 0.f, l1 = 0.f;

    const float* Kg = KV + (size_t)b * TT * KVDIM + kvh * HD;
    const float* Vg = Kg + NKV * HD;

    const uint32_t sKb = (uint32_t)__cvta_generic_to_shared(sK);
    const uint32_t sVb = (uint32_t)__cvta_generic_to_shared(sV);
    const int lo_src = (lane & 28) + (q4 >> 1);
    const bool sel_odd = (q4 & 1);

    const int ntiles = qm / 64 + 1;
    for (int t = 0; t < ntiles; t++) {
        const int n0 = t * 64;
        __syncthreads();

        for (int i = tid; i < 2048; i += 128) {
            int r = i >> 5, c4 = i & 31;
            float4 v = *(const float4*)(Kg + (size_t)(n0 + r) * KVDIM + c4 * 4);
            ((uint4*)sK)[r * (KS_STR / 4) + c4] =
                make_uint4(f2tf(v.x), f2tf(v.y), f2tf(v.z), f2tf(v.w));
        }
        for (int i = tid; i < 2048; i += 128) {
            int key = i & 63, c4 = i >> 6;
            float4 v = *(const float4*)(Vg + (size_t)(n0 + key) * KVDIM + c4 * 4);
            sV[(c4 * 4 + 0) * VT_STR + key] = f2tf(v.x);
            sV[(c4 * 4 + 1) * VT_STR + key] = f2tf(v.y);
            sV[(c4 * 4 + 2) * VT_STR + key] = f2tf(v.z);
            sV[(c4 * 4 + 3) * VT_STR + key] = f2tf(v.w);
        }
        __syncthreads();

        float s[8][4];
#pragma unroll
        for (int j = 0; j < 8; j++)
#pragma unroll
            for (int r = 0; r < 4; r++) s[j][r] = 0.f;
#pragma unroll
        for (int ks = 0; ks < 16; ks++) {
            uint32_t kb[4][4];
#pragma unroll
            for (int jj = 0; jj < 4; jj++) {
                uint32_t addr = sKb + 4u * ((16 * jj + b_row) * KS_STR + 8 * ks + b_chunk);
                ldsm_x4(kb[jj][0], kb[jj][1], kb[jj][2], kb[jj][3], addr);
            }
#pragma unroll
            for (int jj = 0; jj < 4; jj++) {
                mma_tf32a(s[2 * jj + 0], qf[ks], kb[jj][0], kb[jj][1]);
                mma_tf32a(s[2 * jj + 1], qf[ks], kb[jj][2], kb[jj][3]);
            }
        }

        float mt0 = -INFINITY, mt1 = -INFINITY;
#pragma unroll
        for (int j = 0; j < 8; j++) {
            int c0 = n0 + 8 * j + 2 * q4, c1 = c0 + 1;
            if (c0 > r0) s[j][0] = -1e30f;
            if (c1 > r0) s[j][1] = -1e30f;
            if (c0 > r1) s[j][2] = -1e30f;
            if (c1 > r1) s[j][3] = -1e30f;
            mt0 = fmaxf(mt0, fmaxf(s[j][0], s[j][1]));
            mt1 = fmaxf(mt1, fmaxf(s[j][2], s[j][3]));
        }
        mt0 = fmaxf(mt0, __shfl_xor_sync(0xffffffffu, mt0, 1));
        mt0 = fmaxf(mt0, __shfl_xor_sync(0xffffffffu, mt0, 2));
        mt1 = fmaxf(mt1, __shfl_xor_sync(0xffffffffu, mt1, 1));
        mt1 = fmaxf(mt1, __shfl_xor_sync(0xffffffffu, mt1, 2));
        float mn0 = fmaxf(m0, mt0), mn1 = fmaxf(m1, mt1);
        float al0 = __expf(m0 - mn0), al1 = __expf(m1 - mn1);
        m0 = mn0; m1 = mn1;
        float ls0 = 0.f, ls1 = 0.f;
#pragma unroll
        for (int j = 0; j < 8; j++) {
            s[j][0] = __expf(s[j][0] - mn0); ls0 += s[j][0];
            s[j][1] = __expf(s[j][1] - mn0); ls0 += s[j][1];
            s[j][2] = __expf(s[j][2] - mn1); ls1 += s[j][2];
            s[j][3] = __expf(s[j][3] - mn1); ls1 += s[j][3];
        }
        l0 = l0 * al0 + ls0;
        l1 = l1 * al1 + ls1;
#pragma unroll
        for (int i = 0; i < 16; i++) {
            o[i][0] *= al0; o[i][1] *= al0;
            o[i][2] *= al1; o[i][3] *= al1;
        }

#pragma unroll
        for (int ks = 0; ks < 8; ks++) {
            float v00 = __shfl_sync(0xffffffffu, s[ks][0], lo_src);
            float v01 = __shfl_sync(0xffffffffu, s[ks][1], lo_src);
            float v02 = __shfl_sync(0xffffffffu, s[ks][2], lo_src);
            float v03 = __shfl_sync(0xffffffffu, s[ks][3], lo_src);
            float w00 = __shfl_sync(0xffffffffu, s[ks][0], lo_src + 2);
            float w01 = __shfl_sync(0xffffffffu, s[ks][1], lo_src + 2);
            float w02 = __shfl_sync(0xffffffffu, s[ks][2], lo_src + 2);
            float w03 = __shfl_sync(0xffffffffu, s[ks][3], lo_src + 2);
            uint32_t pa[4];
            pa[0] = f2tf(sel_odd ? v01 : v00);
            pa[1] = f2tf(sel_odd ? v03 : v02);
            pa[2] = f2tf(sel_odd ? w01 : w00);
            pa[3] = f2tf(sel_odd ? w03 : w02);
#pragma unroll
            for (int dd = 0; dd < 8; dd++) {
                uint32_t vb0, vb1, vb2, vb3;
                uint32_t addr = sVb + 4u * ((16 * dd + b_row) * VT_STR + 8 * ks + b_chunk);
                ldsm_x4(vb0, vb1, vb2, vb3, addr);
                mma_tf32a(o[2 * dd + 0], pa, vb0, vb1);
                mma_tf32a(o[2 * dd + 1], pa, vb2, vb3);
            }
        }
    }

    l0 += __shfl_xor_sync(0xffffffffu, l0, 1);
    l0 += __shfl_xor_sync(0xffffffffu, l0, 2);
    l1 += __shfl_xor_sync(0xffffffffu, l1, 1);
    l1 += __shfl_xor_sync(0xffffffffu, l1, 2);
    const float i0 = 1.f / l0, i1 = 1.f / l1;

    float* O0 = O + ((size_t)(b * TT) + r0) * QDIM + h * HD;
    float* O1 = O + ((size_t)(b * TT) + r1) * QDIM + h * HD;
#pragma unroll
    for (int dd = 0; dd < 16; dd++) {
        *(float2*)(O0 + 8 * dd + 2 * q4) =
            make_float2(__uint_as_float(f2tf(o[dd][0] * i0)), __uint_as_float(f2tf(o[dd][1] * i0)));
        *(float2*)(O1 + 8 * dd + 2 * q4) =
            make_float2(__uint_as_float(f2tf(o[dd][2] * i1)), __uint_as_float(f2tf(o[dd][3] * i1)));
    }
}

// ---------------------------------------------------------------------------

extern "C" void kernel_launch(void* const* d_in, const int* in_sizes, int n_in,
                              void* d_out, int out_size)
{
    const float* x   = (const float*)d_in[0];
    const float* wq  = (const float*)d_in[1];
    const float* wkv = (const float*)d_in[2];
    const float* wo  = (const float*)d_in[3];
    float* out = (float*)d_out;

    float *Qb, *KVb, *Ob, *xt, *wqt, *wkvt, *wot;
    cudaGetSymbolAddress((void**)&Qb,   g_Q);
    cudaGetSymbolAddress((void**)&KVb,  g_KV);
    cudaGetSymbolAddress((void**)&Ob,   g_O);
    cudaGetSymbolAddress((void**)&xt,   g_xt);
    cudaGetSymbolAddress((void**)&wqt,  g_wqt);
    cudaGetSymbolAddress((void**)&wkvt, g_wkvt);
    cudaGetSymbolAddress((void**)&wot,  g_wot);

    // Pre-round inputs to tf32 (once per launch; DMA-able by cp.async GEMM)
    cvt_tf32_k<<<(MTOT*HIDDEN/4 + 255)/256, 256>>>((const float4*)x,   (float4*)xt,   MTOT*HIDDEN/4);
    cvt_tf32_k<<<(QDIM*HIDDEN/4 + 255)/256, 256>>>((const float4*)wq,  (float4*)wqt,  QDIM*HIDDEN/4);
    cvt_tf32_k<<<(KVDIM*HIDDEN/4 + 255)/256, 256>>>((const float4*)wkv,(float4*)wkvt, KVDIM*HIDDEN/4);
    cvt_tf32_k<<<(HIDDEN*QDIM/4 + 255)/256, 256>>>((const float4*)wo,  (float4*)wot,  HIDDEN*QDIM/4);

    cudaFuncSetAttribute(gemm_qkv, cudaFuncAttributeMaxDynamicSharedMemorySize, GEMM_SMEM);
    cudaFuncSetAttribute(gemm_o,   cudaFuncAttributeMaxDynamicSharedMemorySize, GEMM_SMEM);
    cudaFuncSetAttribute(attn_mma, cudaFuncAttributeMaxDynamicSharedMemorySize, ATTN_SMEM);

    // Fused Q + KV projection
    gemm_qkv<<<dim3(QDIM/128 + KVDIM/128, MTOT/128), 256, GEMM_SMEM>>>(xt, wqt, wkvt, Qb, KVb);

    // Attention (writes tf32-rounded output)
    attn_mma<<<dim3(TT/64, BB*NH), 128, ATTN_SMEM>>>(Qb, KVb, Ob);

    // Output projection
    gemm_o<<<dim3(QDIM/128, MTOT/128), 256, GEMM_SMEM>>>(Ob, wot, out);
}